// round 3
// baseline (speedup 1.0000x reference)
#include <cuda_runtime.h>
#include <math_constants.h>

#define BETA_MIN 0.1f
#define BETA_MAX 20.0f

#define DDIM 128
#define BM 32
#define BN 64
#define NTHREADS 256
#define MAX_M 16384

// Scratch (static __device__ globals are the allowed scratch mechanism)
__device__ float g_y2[MAX_M];                      // ||y_m||^2
__device__ float g_yT[(size_t)DDIM * MAX_M];       // Y transposed [d][m]

// ---------------------------------------------------------------------------
// Precompute 1: y2[m] = sum_d Y[m][d]^2   (one warp per row)
// ---------------------------------------------------------------------------
__global__ void gmm_y2_kernel(const float* __restrict__ Y, int M) {
    int row = blockIdx.x * 8 + threadIdx.y;
    if (row >= M) return;
    int l = threadIdx.x;
    float4 v = *reinterpret_cast<const float4*>(Y + (size_t)row * DDIM + l * 4);
    float s = v.x * v.x + v.y * v.y + v.z * v.z + v.w * v.w;
#pragma unroll
    for (int off = 16; off > 0; off >>= 1)
        s += __shfl_xor_sync(0xffffffffu, s, off);
    if (l == 0) g_y2[row] = s;
}

// ---------------------------------------------------------------------------
// Precompute 2: g_yT[d][m] = Y[m][d]  (smem tiled transpose, 32x32 tiles)
// ---------------------------------------------------------------------------
__global__ void gmm_transpose_kernel(const float* __restrict__ Y, int M) {
    __shared__ float tile[32][33];
    int m0 = blockIdx.x * 32;
    int d0 = blockIdx.y * 32;
    int tx = threadIdx.x, ty = threadIdx.y;
#pragma unroll
    for (int j = ty; j < 32; j += 8)
        tile[j][tx] = Y[(size_t)(m0 + j) * DDIM + d0 + tx];
    __syncthreads();
#pragma unroll
    for (int j = ty; j < 32; j += 8)
        g_yT[(size_t)(d0 + j) * M + m0 + tx] = tile[tx][j];
}

// ---------------------------------------------------------------------------
// Main fused kernel: online-softmax attention over all M keys.
//   score[r][c] = a_r * <x_r, y_c> + b_r * ||y_c||^2   (constant term dropped)
//   out[r][:]   = (softmax_row @ Y - x_r) * inv_var_r
// ---------------------------------------------------------------------------
__global__ __launch_bounds__(NTHREADS, 1)
void gmm_main_kernel(const float* __restrict__ X, const float* __restrict__ T,
                     const float* __restrict__ Y, float* __restrict__ out, int M) {
    extern __shared__ float sm[];
    float* sh_xsT = sm;                 // [128][32]  a_r * x_r, transposed
    float* sh_yT  = sm + 4096;          // [128][64]  Y tile transposed (GEMM1)
    float* sh_yn  = sm + 12288;         // [64][128]  Y tile row-major (GEMM2)
    float* sh_p   = sm + 20480;         // [64][36]   P transposed [c][r], padded
    float* sh_y2  = sm + 22784;         // [64]

    __shared__ float sh_b[BM], sh_inv[BM], sh_a[BM];
    __shared__ float sh_m[BM], sh_l[BM], sh_scale[BM], sh_mnew[BM];
    __shared__ float sh_wmax[2][BM], sh_wsum[2][BM];

    const int tid  = threadIdx.x;
    const int lane = tid & 31;
    const int wid  = tid >> 5;
    const int r0   = blockIdx.x * BM;

    // Per-row VP-SDE marginals
    if (tid < BM) {
        float tv   = T[r0 + tid];
        float lm   = -0.25f * tv * tv * (BETA_MAX - BETA_MIN) - 0.5f * tv * BETA_MIN;
        float mean = expf(lm);
        float em2  = expf(2.0f * lm);
        float var  = fmaxf(1.0f - em2, 1e-12f);
        float inv  = 1.0f / var;
        sh_a[tid]   = mean * inv;
        sh_b[tid]   = -0.5f * mean * mean * inv;
        sh_inv[tid] = inv;
        sh_m[tid]   = -CUDART_INF_F;
        sh_l[tid]   = 0.0f;
    }
    __syncthreads();

    // Build xsT[d][r] = a_r * x[r][d]
    {
        int d4 = lane * 4;
#pragma unroll
        for (int it = 0; it < 4; it++) {
            int r = it * 8 + wid;
            float4 v = *reinterpret_cast<const float4*>(X + (size_t)(r0 + r) * DDIM + d4);
            float a = sh_a[r];
            sh_xsT[(d4 + 0) * BM + r] = a * v.x;
            sh_xsT[(d4 + 1) * BM + r] = a * v.y;
            sh_xsT[(d4 + 2) * BM + r] = a * v.z;
            sh_xsT[(d4 + 3) * BM + r] = a * v.w;
        }
    }

    // GEMM2 accumulators: rows 4*wid..+3, dims 4*lane..+3
    float acc[4][4];
#pragma unroll
    for (int i = 0; i < 4; i++)
#pragma unroll
        for (int j = 0; j < 4; j++) acc[i][j] = 0.f;

    const int h    = wid >> 2;          // GEMM1 column half (0/1)
    const int rblk = (wid & 3) * 8;     // GEMM1 row block (8 rows)
    const int c1   = h * 32 + lane;     // GEMM1 column within tile

    const int ntiles = M / BN;
    for (int tile = 0; tile < ntiles; tile++) {
        const int c0 = tile * BN;
        __syncthreads();  // previous iteration's consumers done with smem tiles

        // Load yT tile [128][64] from pre-transposed global (coalesced)
        {
            int cg    = (tid & 15) * 4;
            int dbase = tid >> 4;  // 0..15
#pragma unroll
            for (int it = 0; it < 8; it++) {
                int d = it * 16 + dbase;
                float4 v = *reinterpret_cast<const float4*>(&g_yT[(size_t)d * M + c0 + cg]);
                *reinterpret_cast<float4*>(&sh_yT[d * BN + cg]) = v;
            }
        }
        // Load yn tile [64][128] (coalesced)
        {
            int d4 = (tid & 31) * 4;
            int cb = tid >> 5;  // 0..7
#pragma unroll
            for (int it = 0; it < 8; it++) {
                int c = it * 8 + cb;
                float4 v = *reinterpret_cast<const float4*>(Y + (size_t)(c0 + c) * DDIM + d4);
                *reinterpret_cast<float4*>(&sh_yn[c * DDIM + d4]) = v;
            }
        }
        if (tid < BN) sh_y2[tid] = g_y2[c0 + tid];
        __syncthreads();

        // ---- GEMM1: s[r][c1] = sum_d xsT[d][r] * yT[d][c1]
        float s[8];
#pragma unroll
        for (int i = 0; i < 8; i++) s[i] = 0.f;
#pragma unroll 4
        for (int d = 0; d < DDIM; d++) {
            float  yv = sh_yT[d * BN + c1];
            float4 xa = *reinterpret_cast<const float4*>(&sh_xsT[d * BM + rblk]);
            float4 xb = *reinterpret_cast<const float4*>(&sh_xsT[d * BM + rblk + 4]);
            s[0] += xa.x * yv; s[1] += xa.y * yv; s[2] += xa.z * yv; s[3] += xa.w * yv;
            s[4] += xb.x * yv; s[5] += xb.y * yv; s[6] += xb.z * yv; s[7] += xb.w * yv;
        }
        {
            float y2c = sh_y2[c1];
#pragma unroll
            for (int i = 0; i < 8; i++) s[i] += sh_b[rblk + i] * y2c;
        }

        // ---- row max across this warp's 32 columns
        float mx[8];
#pragma unroll
        for (int i = 0; i < 8; i++) mx[i] = s[i];
#pragma unroll
        for (int off = 16; off > 0; off >>= 1) {
#pragma unroll
            for (int i = 0; i < 8; i++)
                mx[i] = fmaxf(mx[i], __shfl_xor_sync(0xffffffffu, mx[i], off));
        }
        if (lane == 0) {
#pragma unroll
            for (int i = 0; i < 8; i++) sh_wmax[h][rblk + i] = mx[i];
        }
        __syncthreads();

        if (tid < BM) {
            float tm = fmaxf(sh_wmax[0][tid], sh_wmax[1][tid]);
            float mo = sh_m[tid];
            float mn = fmaxf(mo, tm);
            sh_scale[tid] = __expf(mo - mn);
            sh_mnew[tid]  = mn;
            sh_m[tid]     = mn;
        }
        __syncthreads();

        // ---- p = exp(s - m_new), write P^T to smem, row sums
        float su[8];
#pragma unroll
        for (int i = 0; i < 8; i++) {
            float p = __expf(s[i] - sh_mnew[rblk + i]);
            sh_p[c1 * 36 + rblk + i] = p;
            su[i] = p;
        }
#pragma unroll
        for (int off = 16; off > 0; off >>= 1) {
#pragma unroll
            for (int i = 0; i < 8; i++)
                su[i] += __shfl_xor_sync(0xffffffffu, su[i], off);
        }
        if (lane == 0) {
#pragma unroll
            for (int i = 0; i < 8; i++) sh_wsum[h][rblk + i] = su[i];
        }
        __syncthreads();

        if (tid < BM)
            sh_l[tid] = sh_l[tid] * sh_scale[tid] + sh_wsum[0][tid] + sh_wsum[1][tid];

        // ---- GEMM2: acc[r][d] = acc*scale + sum_c P[r][c] * yn[c][d]
        {
            float sc[4];
#pragma unroll
            for (int i = 0; i < 4; i++) sc[i] = sh_scale[4 * wid + i];
#pragma unroll
            for (int i = 0; i < 4; i++)
#pragma unroll
                for (int j = 0; j < 4; j++) acc[i][j] *= sc[i];

#pragma unroll 2
            for (int cc = 0; cc < BN; cc++) {
                float4 yv = *reinterpret_cast<const float4*>(&sh_yn[cc * DDIM + 4 * lane]);
                float4 pv = *reinterpret_cast<const float4*>(&sh_p[cc * 36 + 4 * wid]);
                acc[0][0] += pv.x * yv.x; acc[0][1] += pv.x * yv.y;
                acc[0][2] += pv.x * yv.z; acc[0][3] += pv.x * yv.w;
                acc[1][0] += pv.y * yv.x; acc[1][1] += pv.y * yv.y;
                acc[1][2] += pv.y * yv.z; acc[1][3] += pv.y * yv.w;
                acc[2][0] += pv.z * yv.x; acc[2][1] += pv.z * yv.y;
                acc[2][2] += pv.z * yv.z; acc[2][3] += pv.z * yv.w;
                acc[3][0] += pv.w * yv.x; acc[3][1] += pv.w * yv.y;
                acc[3][2] += pv.w * yv.z; acc[3][3] += pv.w * yv.w;
            }
        }
    }

    __syncthreads();  // final l_run ready

    // Epilogue: out = (acc/l - x) * inv_var
#pragma unroll
    for (int i = 0; i < 4; i++) {
        int r = 4 * wid + i;
        float inv_l = 1.0f / sh_l[r];
        float iv    = sh_inv[r];
        float4 xv = *reinterpret_cast<const float4*>(X + (size_t)(r0 + r) * DDIM + 4 * lane);
        float4 o;
        o.x = (acc[i][0] * inv_l - xv.x) * iv;
        o.y = (acc[i][1] * inv_l - xv.y) * iv;
        o.z = (acc[i][2] * inv_l - xv.z) * iv;
        o.w = (acc[i][3] * inv_l - xv.w) * iv;
        *reinterpret_cast<float4*>(out + (size_t)(r0 + r) * DDIM + 4 * lane) = o;
    }
}

// ---------------------------------------------------------------------------
extern "C" void kernel_launch(void* const* d_in, const int* in_sizes, int n_in,
                              void* d_out, int out_size) {
    (void)n_in; (void)out_size;
    const float* x = (const float*)d_in[0];
    const float* t = (const float*)d_in[1];
    const float* y = (const float*)d_in[2];
    float* out = (float*)d_out;

    int N = in_sizes[1];
    int M = in_sizes[2] / DDIM;

    const int smem_bytes = 22848 * 4;  // 91392 B
    cudaFuncSetAttribute(gmm_main_kernel,
                         cudaFuncAttributeMaxDynamicSharedMemorySize, smem_bytes);

    gmm_y2_kernel<<<(M + 7) / 8, dim3(32, 8)>>>(y, M);
    gmm_transpose_kernel<<<dim3(M / 32, DDIM / 32), dim3(32, 8)>>>(y, M);
    gmm_main_kernel<<<N / BM, NTHREADS, smem_bytes>>>(x, t, y, out, M);
}

// round 4
// speedup vs baseline: 1.0014x; 1.0014x over previous
#include <cuda_runtime.h>
#include <math_constants.h>

#define BETA_MIN 0.1f
#define BETA_MAX 20.0f

#define DDIM 128
#define BM 32
#define BN 64
#define NTHREADS 256
#define MAX_M 16384

// Scratch (static __device__ globals are the allowed scratch mechanism)
__device__ float g_y2[MAX_M];                      // ||y_m||^2
__device__ float g_yT[(size_t)DDIM * MAX_M];       // Y transposed [d][m]

// ---------------------------------------------------------------------------
// Precompute 1: y2[m] = sum_d Y[m][d]^2   (one warp per row)
// ---------------------------------------------------------------------------
__global__ void gmm_y2_kernel(const float* __restrict__ Y, int M) {
    int row = blockIdx.x * 8 + threadIdx.y;
    if (row >= M) return;
    int l = threadIdx.x;
    float4 v = *reinterpret_cast<const float4*>(Y + (size_t)row * DDIM + l * 4);
    float s = v.x * v.x + v.y * v.y + v.z * v.z + v.w * v.w;
#pragma unroll
    for (int off = 16; off > 0; off >>= 1)
        s += __shfl_xor_sync(0xffffffffu, s, off);
    if (l == 0) g_y2[row] = s;
}

// ---------------------------------------------------------------------------
// Precompute 2: g_yT[d][m] = Y[m][d]  (smem tiled transpose, 32x32 tiles)
// ---------------------------------------------------------------------------
__global__ void gmm_transpose_kernel(const float* __restrict__ Y, int M) {
    __shared__ float tile[32][33];
    int m0 = blockIdx.x * 32;
    int d0 = blockIdx.y * 32;
    int tx = threadIdx.x, ty = threadIdx.y;
#pragma unroll
    for (int j = ty; j < 32; j += 8)
        tile[j][tx] = Y[(size_t)(m0 + j) * DDIM + d0 + tx];
    __syncthreads();
#pragma unroll
    for (int j = ty; j < 32; j += 8)
        g_yT[(size_t)(d0 + j) * M + m0 + tx] = tile[tx][j];
}

// ---------------------------------------------------------------------------
// Main fused kernel: online-softmax attention over all M keys.
//   score[r][c] = a_r * <x_r, y_c> + b_r * ||y_c||^2   (constant term dropped)
//   out[r][:]   = (softmax_row @ Y - x_r) * inv_var_r
// ---------------------------------------------------------------------------
__global__ __launch_bounds__(NTHREADS, 1)
void gmm_main_kernel(const float* __restrict__ X, const float* __restrict__ T,
                     const float* __restrict__ Y, float* __restrict__ out, int M) {
    extern __shared__ float sm[];
    float* sh_xsT = sm;                 // [128][32]  a_r * x_r, transposed
    float* sh_yT  = sm + 4096;          // [128][64]  Y tile transposed (GEMM1)
    float* sh_yn  = sm + 12288;         // [64][128]  Y tile row-major (GEMM2)
    float* sh_p   = sm + 20480;         // [64][36]   P transposed [c][r], padded
    float* sh_y2  = sm + 22784;         // [64]

    __shared__ float sh_b[BM], sh_inv[BM], sh_a[BM];
    __shared__ float sh_m[BM], sh_l[BM], sh_scale[BM], sh_mnew[BM];
    __shared__ float sh_wmax[2][BM], sh_wsum[2][BM];

    const int tid  = threadIdx.x;
    const int lane = tid & 31;
    const int wid  = tid >> 5;
    const int r0   = blockIdx.x * BM;

    // Per-row VP-SDE marginals
    if (tid < BM) {
        float tv   = T[r0 + tid];
        float lm   = -0.25f * tv * tv * (BETA_MAX - BETA_MIN) - 0.5f * tv * BETA_MIN;
        float mean = expf(lm);
        float em2  = expf(2.0f * lm);
        float var  = fmaxf(1.0f - em2, 1e-12f);
        float inv  = 1.0f / var;
        sh_a[tid]   = mean * inv;
        sh_b[tid]   = -0.5f * mean * mean * inv;
        sh_inv[tid] = inv;
        sh_m[tid]   = -CUDART_INF_F;
        sh_l[tid]   = 0.0f;
    }
    __syncthreads();

    // Build xsT[d][r] = a_r * x[r][d]
    {
        int d4 = lane * 4;
#pragma unroll
        for (int it = 0; it < 4; it++) {
            int r = it * 8 + wid;
            float4 v = *reinterpret_cast<const float4*>(X + (size_t)(r0 + r) * DDIM + d4);
            float a = sh_a[r];
            sh_xsT[(d4 + 0) * BM + r] = a * v.x;
            sh_xsT[(d4 + 1) * BM + r] = a * v.y;
            sh_xsT[(d4 + 2) * BM + r] = a * v.z;
            sh_xsT[(d4 + 3) * BM + r] = a * v.w;
        }
    }

    // GEMM2 accumulators: rows 4*wid..+3, dims 4*lane..+3
    float acc[4][4];
#pragma unroll
    for (int i = 0; i < 4; i++)
#pragma unroll
        for (int j = 0; j < 4; j++) acc[i][j] = 0.f;

    const int h    = wid >> 2;          // GEMM1 column half (0/1)
    const int rblk = (wid & 3) * 8;     // GEMM1 row block (8 rows)
    const int c1   = h * 32 + lane;     // GEMM1 column within tile

    const int ntiles = M / BN;
    for (int tile = 0; tile < ntiles; tile++) {
        const int c0 = tile * BN;
        __syncthreads();  // previous iteration's consumers done with smem tiles

        // Load yT tile [128][64] from pre-transposed global (coalesced)
        {
            int cg    = (tid & 15) * 4;
            int dbase = tid >> 4;  // 0..15
#pragma unroll
            for (int it = 0; it < 8; it++) {
                int d = it * 16 + dbase;
                float4 v = *reinterpret_cast<const float4*>(&g_yT[(size_t)d * M + c0 + cg]);
                *reinterpret_cast<float4*>(&sh_yT[d * BN + cg]) = v;
            }
        }
        // Load yn tile [64][128] (coalesced)
        {
            int d4 = (tid & 31) * 4;
            int cb = tid >> 5;  // 0..7
#pragma unroll
            for (int it = 0; it < 8; it++) {
                int c = it * 8 + cb;
                float4 v = *reinterpret_cast<const float4*>(Y + (size_t)(c0 + c) * DDIM + d4);
                *reinterpret_cast<float4*>(&sh_yn[c * DDIM + d4]) = v;
            }
        }
        if (tid < BN) sh_y2[tid] = g_y2[c0 + tid];
        __syncthreads();

        // ---- GEMM1: s[r][c1] = sum_d xsT[d][r] * yT[d][c1]
        float s[8];
#pragma unroll
        for (int i = 0; i < 8; i++) s[i] = 0.f;
#pragma unroll 4
        for (int d = 0; d < DDIM; d++) {
            float  yv = sh_yT[d * BN + c1];
            float4 xa = *reinterpret_cast<const float4*>(&sh_xsT[d * BM + rblk]);
            float4 xb = *reinterpret_cast<const float4*>(&sh_xsT[d * BM + rblk + 4]);
            s[0] += xa.x * yv; s[1] += xa.y * yv; s[2] += xa.z * yv; s[3] += xa.w * yv;
            s[4] += xb.x * yv; s[5] += xb.y * yv; s[6] += xb.z * yv; s[7] += xb.w * yv;
        }
        {
            float y2c = sh_y2[c1];
#pragma unroll
            for (int i = 0; i < 8; i++) s[i] += sh_b[rblk + i] * y2c;
        }

        // ---- row max across this warp's 32 columns
        float mx[8];
#pragma unroll
        for (int i = 0; i < 8; i++) mx[i] = s[i];
#pragma unroll
        for (int off = 16; off > 0; off >>= 1) {
#pragma unroll
            for (int i = 0; i < 8; i++)
                mx[i] = fmaxf(mx[i], __shfl_xor_sync(0xffffffffu, mx[i], off));
        }
        if (lane == 0) {
#pragma unroll
            for (int i = 0; i < 8; i++) sh_wmax[h][rblk + i] = mx[i];
        }
        __syncthreads();

        if (tid < BM) {
            float tm = fmaxf(sh_wmax[0][tid], sh_wmax[1][tid]);
            float mo = sh_m[tid];
            float mn = fmaxf(mo, tm);
            sh_scale[tid] = __expf(mo - mn);
            sh_mnew[tid]  = mn;
            sh_m[tid]     = mn;
        }
        __syncthreads();

        // ---- p = exp(s - m_new), write P^T to smem, row sums
        float su[8];
#pragma unroll
        for (int i = 0; i < 8; i++) {
            float p = __expf(s[i] - sh_mnew[rblk + i]);
            sh_p[c1 * 36 + rblk + i] = p;
            su[i] = p;
        }
#pragma unroll
        for (int off = 16; off > 0; off >>= 1) {
#pragma unroll
            for (int i = 0; i < 8; i++)
                su[i] += __shfl_xor_sync(0xffffffffu, su[i], off);
        }
        if (lane == 0) {
#pragma unroll
            for (int i = 0; i < 8; i++) sh_wsum[h][rblk + i] = su[i];
        }
        __syncthreads();

        if (tid < BM)
            sh_l[tid] = sh_l[tid] * sh_scale[tid] + sh_wsum[0][tid] + sh_wsum[1][tid];

        // ---- GEMM2: acc[r][d] = acc*scale + sum_c P[r][c] * yn[c][d]
        {
            float sc[4];
#pragma unroll
            for (int i = 0; i < 4; i++) sc[i] = sh_scale[4 * wid + i];
#pragma unroll
            for (int i = 0; i < 4; i++)
#pragma unroll
                for (int j = 0; j < 4; j++) acc[i][j] *= sc[i];

#pragma unroll 2
            for (int cc = 0; cc < BN; cc++) {
                float4 yv = *reinterpret_cast<const float4*>(&sh_yn[cc * DDIM + 4 * lane]);
                float4 pv = *reinterpret_cast<const float4*>(&sh_p[cc * 36 + 4 * wid]);
                acc[0][0] += pv.x * yv.x; acc[0][1] += pv.x * yv.y;
                acc[0][2] += pv.x * yv.z; acc[0][3] += pv.x * yv.w;
                acc[1][0] += pv.y * yv.x; acc[1][1] += pv.y * yv.y;
                acc[1][2] += pv.y * yv.z; acc[1][3] += pv.y * yv.w;
                acc[2][0] += pv.z * yv.x; acc[2][1] += pv.z * yv.y;
                acc[2][2] += pv.z * yv.z; acc[2][3] += pv.z * yv.w;
                acc[3][0] += pv.w * yv.x; acc[3][1] += pv.w * yv.y;
                acc[3][2] += pv.w * yv.z; acc[3][3] += pv.w * yv.w;
            }
        }
    }

    __syncthreads();  // final l_run ready

    // Epilogue: out = (acc/l - x) * inv_var
#pragma unroll
    for (int i = 0; i < 4; i++) {
        int r = 4 * wid + i;
        float inv_l = 1.0f / sh_l[r];
        float iv    = sh_inv[r];
        float4 xv = *reinterpret_cast<const float4*>(X + (size_t)(r0 + r) * DDIM + 4 * lane);
        float4 o;
        o.x = (acc[i][0] * inv_l - xv.x) * iv;
        o.y = (acc[i][1] * inv_l - xv.y) * iv;
        o.z = (acc[i][2] * inv_l - xv.z) * iv;
        o.w = (acc[i][3] * inv_l - xv.w) * iv;
        *reinterpret_cast<float4*>(out + (size_t)(r0 + r) * DDIM + 4 * lane) = o;
    }
}

// ---------------------------------------------------------------------------
extern "C" void kernel_launch(void* const* d_in, const int* in_sizes, int n_in,
                              void* d_out, int out_size) {
    (void)n_in; (void)out_size;
    const float* x = (const float*)d_in[0];
    const float* t = (const float*)d_in[1];
    const float* y = (const float*)d_in[2];
    float* out = (float*)d_out;

    int N = in_sizes[1];
    int M = in_sizes[2] / DDIM;

    const int smem_bytes = 22848 * 4;  // 91392 B
    cudaFuncSetAttribute(gmm_main_kernel,
                         cudaFuncAttributeMaxDynamicSharedMemorySize, smem_bytes);

    gmm_y2_kernel<<<(M + 7) / 8, dim3(32, 8)>>>(y, M);
    gmm_transpose_kernel<<<dim3(M / 32, DDIM / 32), dim3(32, 8)>>>(y, M);
    gmm_main_kernel<<<N / BM, NTHREADS, smem_bytes>>>(x, t, y, out, M);
}